// round 11
// baseline (speedup 1.0000x reference)
#include <cuda_runtime.h>
#include <math.h>
#include <stdint.h>

#define Bn 128
#define Tn 1024
#define Hn 512

// Packed dual-FMA: acc(f32x2) += a(f32x2) * b(f32x2), IEEE fp32 per lane.
#define FMA2(acc, a, b) \
    asm("fma.rn.f32x2 %0, %1, %2, %0;" : "+l"(acc) : "l"(a), "l"(b))
#define DUP2(d, f) \
    asm("mov.b64 %0, {%1, %1};" : "=l"(d) : "f"(f))
#define PACK2(d, lo, hi) \
    asm("mov.b64 %0, {%1, %2};" : "=l"(d) : "f"(lo), "f"(hi))

union UF2 { unsigned long long u; float2 f; };

__device__ unsigned g_cnt[16 * 1024];   // [rg][t] warp arrivals (target 128)

__global__ void zero_cnt() {
    int i = blockIdx.x * blockDim.x + threadIdx.x;
    if (i < 16 * 1024) g_cnt[i] = 0u;
}

__device__ __forceinline__ unsigned ld_acq(const unsigned* p) {
    unsigned v;
    asm volatile("ld.acquire.gpu.global.u32 %0, [%1];" : "=r"(v) : "l"(p));
    return v;
}
__device__ __forceinline__ unsigned ld_rlx(const unsigned* p) {
    unsigned v;
    asm volatile("ld.relaxed.gpu.global.u32 %0, [%1];" : "=r"(v) : "l"(p));
    return v;
}
__device__ __forceinline__ void red_rel(unsigned* p) {
    asm volatile("red.release.gpu.global.add.u32 [%0], 1;" :: "l"(p) : "memory");
}
__device__ __forceinline__ void cp16(uint32_t s, const void* g) {
    asm volatile("cp.async.cg.shared.global [%0], [%1], 16;" :: "r"(s), "l"(g));
}
#define CP_COMMIT() asm volatile("cp.async.commit_group;" ::: "memory")
#define CP_WAIT0()  asm volatile("cp.async.wait_group 0;" ::: "memory")

// ---------------------------------------------------------------------------
// Phase 1: pre[t][b][:] = X[b][t][:] @ Wx + bias  (into d_out, [T,B,H])
// BM=128, BN=128, BK=32, 256 threads, 8x8/thread.
// 2-stage cp.async pipeline: tile it+1 streams in under tile-it compute;
// ONE wait_group+syncthreads per iteration (16 total).
// ---------------------------------------------------------------------------
#define BK   32
#define AST  36                     // As row stride (floats), row-major [row][k]
#define BST  132                    // Bs row stride (floats), [k][col]
#define ABUF (128 * AST)            // 4608
#define BBUF (BK * BST)             // 4224
#define GEMM_SMEM_BYTES ((2 * ABUF + 2 * BBUF) * 4)   // 70656

__global__ __launch_bounds__(256) void gemm_xw(
    const float* __restrict__ X,    // [B*T, H] rows r = b*T + t
    const float* __restrict__ Wx,   // [H, H]
    const float* __restrict__ bias, // [H]
    float* __restrict__ out)        // [T, B, H]
{
    extern __shared__ float smg[];
    float* As = smg;                // [2][128][AST]
    float* Bs = smg + 2 * ABUF;     // [2][BK][BST]

    const int bm0 = blockIdx.y * 128;
    const int bn0 = blockIdx.x * 128;
    const int tid = threadIdx.x;
    const int tr  = (tid >> 4) << 3;
    const int tc  = (tid & 15) << 3;

    // staging indices (4 x 16B for A, 4 x 16B for B per thread per tile)
    const int a_r  = tid >> 3;             // with +32*i: rows 0..127
    const int a_k4 = (tid & 7) << 2;       // 0..28
    const int b_k  = tid >> 5;             // with +8*i: k 0..31
    const int b_c4 = (tid & 31) << 2;      // 0..124

    unsigned as_base = (unsigned)__cvta_generic_to_shared(As);
    unsigned bs_base = (unsigned)__cvta_generic_to_shared(Bs);

#define STAGE(it, buf)                                                          \
    do {                                                                        \
        const int k0s = (it) * BK;                                              \
        _Pragma("unroll")                                                       \
        for (int i = 0; i < 4; i++) {                                           \
            int r = a_r + (i << 5);                                             \
            cp16(as_base + (unsigned)(((buf) * ABUF + r * AST + a_k4) * 4),     \
                 X + (size_t)(bm0 + r) * Hn + k0s + a_k4);                      \
        }                                                                       \
        _Pragma("unroll")                                                       \
        for (int i = 0; i < 4; i++) {                                           \
            int kk = b_k + (i << 3);                                            \
            cp16(bs_base + (unsigned)(((buf) * BBUF + kk * BST + b_c4) * 4),    \
                 Wx + (size_t)(k0s + kk) * Hn + bn0 + b_c4);                    \
        }                                                                       \
        CP_COMMIT();                                                            \
    } while (0)

    unsigned long long acc2[8][4];
#pragma unroll
    for (int i = 0; i < 8; i++)
#pragma unroll
        for (int j = 0; j < 4; j++) acc2[i][j] = 0ull;

    STAGE(0, 0);
    CP_WAIT0();
    __syncthreads();

    for (int it = 0; it < 16; it++) {
        if (it + 1 < 16) STAGE(it + 1, (it + 1) & 1);

        const float* Ab = As + (it & 1) * ABUF;
        const float* Bb = Bs + (it & 1) * BBUF;
#pragma unroll 8
        for (int kk = 0; kk < BK; kk++) {
            ulonglong2 bv0 = *(const ulonglong2*)&Bb[kk * BST + tc];
            ulonglong2 bv1 = *(const ulonglong2*)&Bb[kk * BST + tc + 4];
#pragma unroll
            for (int i = 0; i < 8; i++) {
                unsigned long long d;
                DUP2(d, Ab[(tr + i) * AST + kk]);
                FMA2(acc2[i][0], d, bv0.x);
                FMA2(acc2[i][1], d, bv0.y);
                FMA2(acc2[i][2], d, bv1.x);
                FMA2(acc2[i][3], d, bv1.y);
            }
        }

        if (it + 1 < 16) {
            CP_WAIT0();                 // tile it+1 landed (hidden under compute)
            __syncthreads();
        }
    }

    float4 bb0 = *(const float4*)(bias + bn0 + tc);
    float4 bb1 = *(const float4*)(bias + bn0 + tc + 4);
#pragma unroll
    for (int i = 0; i < 8; i++) {
        int m = bm0 + tr + i;
        int b = m >> 10;                // T = 1024
        int t = m & 1023;
        UF2 q0, q1, q2, q3;
        q0.u = acc2[i][0];
        q1.u = acc2[i][1];
        q2.u = acc2[i][2];
        q3.u = acc2[i][3];
        float4 o0, o1;
        o0.x = q0.f.x + bb0.x;
        o0.y = q0.f.y + bb0.y;
        o0.z = q1.f.x + bb0.z;
        o0.w = q1.f.y + bb0.w;
        o1.x = q2.f.x + bb1.x;
        o1.y = q2.f.y + bb1.y;
        o1.z = q3.f.x + bb1.z;
        o1.w = q3.f.y + bb1.w;
        float* dst = out + ((size_t)t * Bn + b) * Hn + bn0 + tc;
        *(float4*)(dst)     = o0;
        *(float4*)(dst + 4) = o1;
    }
}

// ---------------------------------------------------------------------------
// Phase 2: persistent RNN (R10 structure), de-convoyed tail:
//  - per-WARP arrival: after a warp's output stores, lane0 fires
//    red.release.gpu (no return, no fence, no CTA barrier). Target = 128.
//  - poll: relaxed spin + one acquire confirm.
// Safe: passing poll(t) requires all 128 warps of the rowgroup (incl. own
// CTA's 16) to have finished reading Ps/Sw at t, so next-step overwrites race
// nothing. Only ONE __syncthreads per step remains (partials -> reduce).
// ---------------------------------------------------------------------------
#define SWSTR 36                          // per-warp state row stride (floats)
#define SW_FLOATS (8 * SWSTR)             // 288 per warp
#define PSQ 544                           // partials per k-chunk (8 x 68)
#define RNN_SMEM_BYTES ((16 * SW_FLOATS + 16 * PSQ) * 4)   // 53248

__global__ __launch_bounds__(512) void rnn_steps(
    const float* __restrict__ state0,  // [B, H]
    const float* __restrict__ Wh,      // [H, H]
    float* __restrict__ out)           // [T, B, H] (holds pre on entry)
{
    extern __shared__ float sm[];
    float* SwA = sm;                      // [16][8][36] per-warp state chunks
    float* Ps  = sm + 16 * SW_FLOATS;     // [16][8][68] k-chunk partials

    const int tid  = threadIdx.x;
    const int w    = tid >> 5;            // warp = k-chunk [32w, 32w+32)
    const int lane = tid & 31;
    const int cg   = blockIdx.x & 7;
    const int rg   = blockIdx.x >> 3;
    const int c0   = cg * 64;
    const int r0   = rg * 8;

    // weights: thread covers cols {gc, gc+1}, k in [32w, 32w+32)
    const int gc = c0 + lane * 2;
    unsigned long long w2a[16], w2b[16];
    {
        const float* wb = Wh + (size_t)(w * 32) * Hn + gc;
#pragma unroll
        for (int j = 0; j < 16; j++) {
            float a0 = wb[(2 * j) * Hn];
            float a1 = wb[(2 * j + 1) * Hn];
            float b0 = wb[(2 * j) * Hn + 1];
            float b1 = wb[(2 * j + 1) * Hn + 1];
            PACK2(w2a[j], a0, a1);
            PACK2(w2b[j], b0, b1);
        }
    }

    // epilogue mapping: one output element per thread
    const int rr = tid >> 6;              // 0..7
    const int cc = tid & 63;              // 0..63
    float* opbase = out + (size_t)(r0 + rr) * Hn + c0 + cc;

    // self-staging mapping: warp w loads rows 0..7 x k[32w,32w+32)
    const int sr  = lane >> 3;            // 0..3  (and +4 on second load)
    const int sk4 = (lane & 7) << 2;      // 0..28

    float* Sw = SwA + w * SW_FLOATS;
    unsigned* cnt = &g_cnt[rg * 1024];

    for (int t = 0; t < Tn; t++) {
        float* op = opbase + (size_t)t * (Bn * Hn);
        float pre = __ldcg(op);           // pre-activation (overlaps the poll)

        // ---- relaxed poll for peers' step t-1, acquire on exit ----
        if (t > 0) {
            while (ld_rlx(&cnt[t - 1]) < 128u) { }
            (void)ld_acq(&cnt[t - 1]);
        }

        // ---- self-stage own k-chunk ----
        const float* prev = (t == 0) ? state0
                                     : (out + (size_t)(t - 1) * (Bn * Hn));
        {
            const float* pk = prev + (size_t)r0 * Hn + w * 32 + sk4;
            float4 v0 = __ldcg((const float4*)(pk + (size_t)sr * Hn));
            float4 v1 = __ldcg((const float4*)(pk + (size_t)(sr + 4) * Hn));
            *(float4*)(Sw + sr * SWSTR + sk4)       = v0;
            *(float4*)(Sw + (sr + 4) * SWSTR + sk4) = v1;
        }
        __syncwarp();

        // ---- FMA: 8 rows x 2 cols x 32 k per thread ----
        unsigned long long acc[8][2];
#pragma unroll
        for (int r = 0; r < 8; r++) { acc[r][0] = 0ull; acc[r][1] = 0ull; }
#pragma unroll
        for (int jj = 0; jj < 8; jj++) {
            const int k = jj * 4;
#pragma unroll
            for (int r = 0; r < 8; r++) {
                ulonglong2 sv = *(const ulonglong2*)(Sw + r * SWSTR + k);
                FMA2(acc[r][0], sv.x, w2a[2 * jj]);
                FMA2(acc[r][0], sv.y, w2a[2 * jj + 1]);
                FMA2(acc[r][1], sv.x, w2b[2 * jj]);
                FMA2(acc[r][1], sv.y, w2b[2 * jj + 1]);
            }
        }

        // ---- partials ----
        {
            float* pb = Ps + w * PSQ + lane * 2;
#pragma unroll
            for (int r = 0; r < 8; r++) {
                UF2 u0, u1;
                u0.u = acc[r][0];
                u1.u = acc[r][1];
                float2 p;
                p.x = u0.f.x + u0.f.y;
                p.y = u1.f.x + u1.f.y;
                *(float2*)(pb + r * 68) = p;
            }
        }
        __syncthreads();                  // the only CTA barrier per step

        // ---- reduce 16 k-chunks + tanh + publish value ----
        {
            const float* pp = Ps + rr * 68 + cc;
            float s = 0.0f;
#pragma unroll
            for (int q = 0; q < 16; q++) s += pp[q * PSQ];
            __stcg(op, tanhf(pre + s));
        }

        // ---- per-warp arrival (fire & forget) ----
        if (t != Tn - 1) {
            __syncwarp();                 // order whole warp's stcg before red
            if (lane == 0) red_rel(&cnt[t]);
        }
    }
}

extern "C" void kernel_launch(void* const* d_in, const int* in_sizes, int n_in,
                              void* d_out, int out_size)
{
    const float* X    = (const float*)d_in[0];  // inputs_tensor [B,T,H]
    const float* S0   = (const float*)d_in[1];  // state_tensor  [1,B,H]
    const float* Wx   = (const float*)d_in[2];  // [H,H]
    const float* Wh   = (const float*)d_in[3];  // [H,H]
    const float* bias = (const float*)d_in[4];  // [H]
    float* out = (float*)d_out;                 // [T,B,H]

    (void)in_sizes; (void)n_in; (void)out_size;

    cudaFuncSetAttribute(gemm_xw,
                         cudaFuncAttributeMaxDynamicSharedMemorySize,
                         GEMM_SMEM_BYTES);
    cudaFuncSetAttribute(rnn_steps,
                         cudaFuncAttributeMaxDynamicSharedMemorySize,
                         RNN_SMEM_BYTES);

    zero_cnt<<<32, 512>>>();

    dim3 g1(Hn / 128, (Bn * Tn) / 128);  // (4, 1024)
    gemm_xw<<<g1, 256, GEMM_SMEM_BYTES>>>(X, Wx, bias, out);

    rnn_steps<<<128, 512, RNN_SMEM_BYTES>>>(S0, Wh, out);
}

// round 12
// speedup vs baseline: 1.0147x; 1.0147x over previous
#include <cuda_runtime.h>
#include <math.h>
#include <stdint.h>

#define Bn 128
#define Tn 1024
#define Hn 512

// Packed dual-FMA: acc(f32x2) += a(f32x2) * b(f32x2), IEEE fp32 per lane.
#define FMA2(acc, a, b) \
    asm("fma.rn.f32x2 %0, %1, %2, %0;" : "+l"(acc) : "l"(a), "l"(b))
#define DUP2(d, f) \
    asm("mov.b64 %0, {%1, %1};" : "=l"(d) : "f"(f))
#define PACK2(d, lo, hi) \
    asm("mov.b64 %0, {%1, %2};" : "=l"(d) : "f"(lo), "f"(hi))

union UF2 { unsigned long long u; float2 f; };

__device__ unsigned g_cnt[16 * 1024];   // [rg][t] CTA arrivals (target 8)

__global__ void zero_cnt() {
    int i = blockIdx.x * blockDim.x + threadIdx.x;
    if (i < 16 * 1024) g_cnt[i] = 0u;
}

__device__ __forceinline__ unsigned ld_acq(const unsigned* p) {
    unsigned v;
    asm volatile("ld.acquire.gpu.global.u32 %0, [%1];" : "=r"(v) : "l"(p));
    return v;
}

// ---------------------------------------------------------------------------
// Phase 1: pre[t][b][:] = X[b][t][:] @ Wx + bias  (into d_out, [T,B,H])
// BM=128, BN=128, BK=16, 256 threads, 8x8/thread. R9's proven transposed-A
// layout + vectorized LDS.128 inner loop, PLUS register double-buffering:
// tile it+1's LDGs are issued before tile it's compute, hiding load latency.
// ---------------------------------------------------------------------------
__global__ __launch_bounds__(256) void gemm_xw(
    const float* __restrict__ X,    // [B*T, H] rows r = b*T + t
    const float* __restrict__ Wx,   // [H, H]
    const float* __restrict__ bias, // [H]
    float* __restrict__ out)        // [T, B, H]
{
    __shared__ float As[16][132];   // [k][row]
    __shared__ float Bs[16][132];   // [k][col]

    const int bm0 = blockIdx.y * 128;
    const int bn0 = blockIdx.x * 128;
    const int tid = threadIdx.x;
    const int tr  = (tid >> 4) << 3;   // row offset 0..120
    const int tc  = (tid & 15) << 3;   // col offset 0..120

    // load mapping (2 float4 for A, 2 for B per thread per tile)
    const int a_row = tid >> 2;                 // f>>2 with f=tid+v*256
    const int a_kk  = (tid & 3) << 2;
    const int b_kk  = tid >> 5;                 // +8 on second
    const int b_col = (tid & 31) << 2;

    unsigned long long acc2[8][4];
#pragma unroll
    for (int i = 0; i < 8; i++)
#pragma unroll
        for (int j = 0; j < 4; j++) acc2[i][j] = 0ull;

    float4 ra[2], rb[2];

    // ---- preload tile 0 into registers ----
    {
        ra[0] = *(const float4*)(X + (size_t)(bm0 + a_row) * Hn + a_kk);
        ra[1] = *(const float4*)(X + (size_t)(bm0 + a_row + 64) * Hn + a_kk);
        rb[0] = *(const float4*)(Wx + (size_t)(b_kk) * Hn + bn0 + b_col);
        rb[1] = *(const float4*)(Wx + (size_t)(b_kk + 8) * Hn + bn0 + b_col);
    }

    for (int it = 0; it < 32; it++) {
        // ---- store current tile regs to smem (A transposed) ----
        As[a_kk + 0][a_row] = ra[0].x;
        As[a_kk + 1][a_row] = ra[0].y;
        As[a_kk + 2][a_row] = ra[0].z;
        As[a_kk + 3][a_row] = ra[0].w;
        As[a_kk + 0][a_row + 64] = ra[1].x;
        As[a_kk + 1][a_row + 64] = ra[1].y;
        As[a_kk + 2][a_row + 64] = ra[1].z;
        As[a_kk + 3][a_row + 64] = ra[1].w;
        *(float4*)&Bs[b_kk][b_col]     = rb[0];
        *(float4*)&Bs[b_kk + 8][b_col] = rb[1];
        __syncthreads();

        // ---- issue next tile's LDGs (latency hidden under compute) ----
        if (it + 1 < 32) {
            const int k0n = (it + 1) * 16;
            ra[0] = *(const float4*)(X + (size_t)(bm0 + a_row) * Hn + k0n + a_kk);
            ra[1] = *(const float4*)(X + (size_t)(bm0 + a_row + 64) * Hn + k0n + a_kk);
            rb[0] = *(const float4*)(Wx + (size_t)(k0n + b_kk) * Hn + bn0 + b_col);
            rb[1] = *(const float4*)(Wx + (size_t)(k0n + b_kk + 8) * Hn + bn0 + b_col);
        }

        // ---- compute 16 kk (R9's proven fragment pattern) ----
#pragma unroll
        for (int kk = 0; kk < 16; kk++) {
            float4 a0 = *(const float4*)&As[kk][tr];
            float4 a1 = *(const float4*)&As[kk][tr + 4];
            ulonglong2 bv0 = *(const ulonglong2*)&Bs[kk][tc];
            ulonglong2 bv1 = *(const ulonglong2*)&Bs[kk][tc + 4];
            float av[8] = {a0.x, a0.y, a0.z, a0.w, a1.x, a1.y, a1.z, a1.w};
#pragma unroll
            for (int i = 0; i < 8; i++) {
                unsigned long long d;
                DUP2(d, av[i]);
                FMA2(acc2[i][0], d, bv0.x);
                FMA2(acc2[i][1], d, bv0.y);
                FMA2(acc2[i][2], d, bv1.x);
                FMA2(acc2[i][3], d, bv1.y);
            }
        }
        __syncthreads();
    }

    float4 bb0 = *(const float4*)(bias + bn0 + tc);
    float4 bb1 = *(const float4*)(bias + bn0 + tc + 4);
#pragma unroll
    for (int i = 0; i < 8; i++) {
        int m = bm0 + tr + i;
        int b = m >> 10;                // T = 1024
        int t = m & 1023;
        UF2 q0, q1, q2, q3;
        q0.u = acc2[i][0];
        q1.u = acc2[i][1];
        q2.u = acc2[i][2];
        q3.u = acc2[i][3];
        float4 o0, o1;
        o0.x = q0.f.x + bb0.x;
        o0.y = q0.f.y + bb0.y;
        o0.z = q1.f.x + bb0.z;
        o0.w = q1.f.y + bb0.w;
        o1.x = q2.f.x + bb1.x;
        o1.y = q2.f.y + bb1.y;
        o1.z = q3.f.x + bb1.z;
        o1.w = q3.f.y + bb1.w;
        float* dst = out + ((size_t)t * Bn + b) * Hn + bn0 + tc;
        *(float4*)(dst)     = o0;
        *(float4*)(dst + 4) = o1;
    }
}

// ---------------------------------------------------------------------------
// Phase 2: persistent RNN — EXACT R10 structure (proven 4456 config).
// 128 CTAs = 16 rowgroups x 8 colgroups; per-rowgroup L2 flag sync.
// All threads acquire-poll cnt[rg][t-1]; each warp self-stages its own
// k-chunk; FMA2; partials -> sync -> reduce+tanh+stcg -> sync -> tid0 arrive.
// ---------------------------------------------------------------------------
#define SWSTR 36                          // per-warp state row stride (floats)
#define SW_FLOATS (8 * SWSTR)             // 288 per warp
#define PSQ 544                           // partials per k-chunk (8 x 68)
#define RNN_SMEM_BYTES ((16 * SW_FLOATS + 16 * PSQ) * 4)   // 53248

__global__ __launch_bounds__(512) void rnn_steps(
    const float* __restrict__ state0,  // [B, H]
    const float* __restrict__ Wh,      // [H, H]
    float* __restrict__ out)           // [T, B, H] (holds pre on entry)
{
    extern __shared__ float sm[];
    float* SwA = sm;                      // [16][8][36] per-warp state chunks
    float* Ps  = sm + 16 * SW_FLOATS;     // [16][8][68] k-chunk partials

    const int tid  = threadIdx.x;
    const int w    = tid >> 5;            // warp = k-chunk [32w, 32w+32)
    const int lane = tid & 31;
    const int cg   = blockIdx.x & 7;
    const int rg   = blockIdx.x >> 3;
    const int c0   = cg * 64;
    const int r0   = rg * 8;

    // weights: thread covers cols {gc, gc+1}, k in [32w, 32w+32)
    const int gc = c0 + lane * 2;
    unsigned long long w2a[16], w2b[16];
    {
        const float* wb = Wh + (size_t)(w * 32) * Hn + gc;
#pragma unroll
        for (int j = 0; j < 16; j++) {
            float a0 = wb[(2 * j) * Hn];
            float a1 = wb[(2 * j + 1) * Hn];
            float b0 = wb[(2 * j) * Hn + 1];
            float b1 = wb[(2 * j + 1) * Hn + 1];
            PACK2(w2a[j], a0, a1);
            PACK2(w2b[j], b0, b1);
        }
    }

    // epilogue mapping: one output element per thread
    const int rr = tid >> 6;              // 0..7
    const int cc = tid & 63;              // 0..63
    float* opbase = out + (size_t)(r0 + rr) * Hn + c0 + cc;

    // self-staging mapping: warp w loads rows 0..7 x k[32w,32w+32)
    const int sr  = lane >> 3;            // 0..3  (and +4 on second load)
    const int sk4 = (lane & 7) << 2;      // 0..28

    float* Sw = SwA + w * SW_FLOATS;
    unsigned* cnt = &g_cnt[rg * 1024];

    for (int t = 0; t < Tn; t++) {
        float* op = opbase + (size_t)t * (Bn * Hn);
        float pre = __ldcg(op);           // pre-activation (written in phase 1)

        // ---- acquire-poll peers' step t-1 (every thread; self-releasing) ----
        if (t > 0) {
            while (ld_acq(&cnt[t - 1]) < 8u) { }
        }

        // ---- self-stage own k-chunk ----
        const float* prev = (t == 0) ? state0
                                     : (out + (size_t)(t - 1) * (Bn * Hn));
        {
            const float* pk = prev + (size_t)r0 * Hn + w * 32 + sk4;
            float4 v0 = __ldcg((const float4*)(pk + (size_t)sr * Hn));
            float4 v1 = __ldcg((const float4*)(pk + (size_t)(sr + 4) * Hn));
            *(float4*)(Sw + sr * SWSTR + sk4)       = v0;
            *(float4*)(Sw + (sr + 4) * SWSTR + sk4) = v1;
        }
        __syncwarp();

        // ---- FMA: 8 rows x 2 cols x 32 k per thread ----
        unsigned long long acc[8][2];
#pragma unroll
        for (int r = 0; r < 8; r++) { acc[r][0] = 0ull; acc[r][1] = 0ull; }
#pragma unroll
        for (int jj = 0; jj < 8; jj++) {
            const int k = jj * 4;
#pragma unroll
            for (int r = 0; r < 8; r++) {
                ulonglong2 sv = *(const ulonglong2*)(Sw + r * SWSTR + k);
                FMA2(acc[r][0], sv.x, w2a[2 * jj]);
                FMA2(acc[r][0], sv.y, w2a[2 * jj + 1]);
                FMA2(acc[r][1], sv.x, w2b[2 * jj]);
                FMA2(acc[r][1], sv.y, w2b[2 * jj + 1]);
            }
        }

        // ---- partials ----
        {
            float* pb = Ps + w * PSQ + lane * 2;
#pragma unroll
            for (int r = 0; r < 8; r++) {
                UF2 u0, u1;
                u0.u = acc[r][0];
                u1.u = acc[r][1];
                float2 p;
                p.x = u0.f.x + u0.f.y;
                p.y = u1.f.x + u1.f.y;
                *(float2*)(pb + r * 68) = p;
            }
        }
        __syncthreads();                  // partials ready

        // ---- reduce 16 k-chunks + tanh + publish value ----
        {
            const float* pp = Ps + rr * 68 + cc;
            float s = 0.0f;
#pragma unroll
            for (int q = 0; q < 16; q++) s += pp[q * PSQ];
            __stcg(op, tanhf(pre + s));
        }
        __syncthreads();                  // stores issued + Ps safe to reuse

        if (t != Tn - 1 && tid == 0) {
            __threadfence();              // publish chunk before arrive
            atomicAdd(&cnt[t], 1u);
        }
    }
}

extern "C" void kernel_launch(void* const* d_in, const int* in_sizes, int n_in,
                              void* d_out, int out_size)
{
    const float* X    = (const float*)d_in[0];  // inputs_tensor [B,T,H]
    const float* S0   = (const float*)d_in[1];  // state_tensor  [1,B,H]
    const float* Wx   = (const float*)d_in[2];  // [H,H]
    const float* Wh   = (const float*)d_in[3];  // [H,H]
    const float* bias = (const float*)d_in[4];  // [H]
    float* out = (float*)d_out;                 // [T,B,H]

    (void)in_sizes; (void)n_in; (void)out_size;

    cudaFuncSetAttribute(rnn_steps,
                         cudaFuncAttributeMaxDynamicSharedMemorySize,
                         RNN_SMEM_BYTES);

    zero_cnt<<<32, 512>>>();

    dim3 g1(Hn / 128, (Bn * Tn) / 128);  // (4, 1024)
    gemm_xw<<<g1, 256>>>(X, Wx, bias, out);

    rnn_steps<<<128, 512, RNN_SMEM_BYTES>>>(S0, Wh, out);
}